// round 5
// baseline (speedup 1.0000x reference)
#include <cuda_runtime.h>
#include <cstdint>

// Problem constants
#define B_   64
#define D_   128
#define T_   2048
#define K_   1024
#define N_   (B_ * T_)            // 131072 tokens
#define ND_  (N_ * D_)            // 16777216
#define DECAYF 0.99f
#define EPSF   1e-5f

#define EPITCH 130                // padded row length for transposed E tile (2-way STS conflict, 8B-aligned rows)

// -------- device scratch (no allocations allowed) --------
__device__ float g_counts[K_];
__device__ float g_dw[K_ * D_];
__device__ float g_e2[K_];
__device__ float g_cs[K_];
__device__ float g_losssum;

// -------- packed f32x2 helpers (FFMA2 path: 2x fp32 FMA rate on sm_103a) --------
__device__ __forceinline__ unsigned long long pack2(float lo, float hi) {
    unsigned long long r;
    asm("mov.b64 %0, {%1, %2};" : "=l"(r) : "f"(lo), "f"(hi));
    return r;
}
__device__ __forceinline__ void unpack2(unsigned long long v, float& lo, float& hi) {
    asm("mov.b64 {%0, %1}, %2;" : "=f"(lo), "=f"(hi) : "l"(v));
}
__device__ __forceinline__ unsigned long long ffma2(unsigned long long a,
                                                    unsigned long long b,
                                                    unsigned long long c) {
    unsigned long long d;
    asm("fma.rn.f32x2 %0, %1, %2, %3;" : "=l"(d) : "l"(a), "l"(b), "l"(c));
    return d;
}

// -------- zero scratch each launch (graph-replayable) --------
__global__ void k_zero() {
    int i = blockIdx.x * blockDim.x + threadIdx.x;
    if (i < K_ * D_) g_dw[i] = 0.0f;
    if (i < K_)      g_counts[i] = 0.0f;
    if (i == 0)      g_losssum = 0.0f;
}

// -------- |e_k|^2 per code (warp per code) --------
__global__ void k_e2(const float* __restrict__ emb) {
    int w    = (blockIdx.x * blockDim.x + threadIdx.x) >> 5;
    int lane = threadIdx.x & 31;
    for (int k = w; k < K_; k += (gridDim.x * blockDim.x) >> 5) {
        float s = 0.0f;
        const float* row = emb + (size_t)k * D_;
        for (int d = lane; d < D_; d += 32) {
            float v = row[d];
            s += v * v;
        }
        #pragma unroll
        for (int off = 16; off >= 1; off >>= 1)
            s += __shfl_xor_sync(0xffffffffu, s, off);
        if (lane == 0) g_e2[k] = s;
    }
}

// -------- main fused kernel: argmin + loss + histogram + dw scatter + quantized output --------
// Block: 128 tokens (one b, contiguous t range) vs all 1024 codes.
// 256 threads, 16x16 thread grid, 8 tokens x 8 codes micro-tile, f32x2 accumulators.
// Distance comparison emulates the reference's fp32 rounding:
//   s_k = fl( fl(|x|^2 + |e_k|^2) - 2*dot_k )   at magnitude ~128 (ulp ~1.5e-5),
// with strict-< / lowest-index tie-break, so rounded ties resolve like jnp.argmin.
__global__ __launch_bounds__(256, 1)
void k_main(const float* __restrict__ x, const float* __restrict__ emb,
            float* __restrict__ out, float* __restrict__ idxOut, int writeAux)
{
    extern __shared__ float sm[];
    float* Xs     = sm;                          // [128 d][128 tok]
    float* Es     = Xs + 128 * 128;              // [128 d][EPITCH codes]
    float* e2s    = Es + 128 * EPITCH;           // 128
    float* tokMin = e2s + 128;                   // 128
    int*   tokIdx = (int*)(tokMin + 128);        // 128
    float* red    = (float*)(tokIdx + 128);      // 256 (also used for xsq partials)
    float* xsqs   = red + 256;                   // 128 per-token |x|^2

    const int tid  = threadIdx.x;
    const int tile = blockIdx.x;
    const int b    = tile >> 4;
    const int t0   = (tile & 15) << 7;

    const float* xbase = x + ((size_t)b * D_) * T_ + t0;

    // ---- load X tile [d][tok] (coalesced float4) ----
    #pragma unroll
    for (int r = 0; r < 16; ++r) {
        int f4 = tid + 256 * r;        // 4096 float4s total
        int d  = f4 >> 5;
        int tt = (f4 & 31) * 4;
        float4 v = *reinterpret_cast<const float4*>(xbase + (size_t)d * T_ + tt);
        *reinterpret_cast<float4*>(&Xs[d * 128 + tt]) = v;
    }
    __syncthreads();

    // ---- per-token |x|^2: two sequential 64-term halves, then combine ----
    {
        int t    = tid >> 1;
        int half = tid & 1;
        float s = 0.0f;
        const float* col = &Xs[(half * 64) * 128 + t];
        #pragma unroll 8
        for (int d = 0; d < 64; ++d) {
            float v = col[d * 128];
            s += v * v;
        }
        red[tid] = s;
    }
    __syncthreads();
    if (tid < 128) xsqs[tid] = red[2 * tid] + red[2 * tid + 1];

    const int tx = tid & 15;
    const int ty = tid >> 4;

    float minv[8];
    int   mini[8];
    #pragma unroll
    for (int i = 0; i < 8; ++i) { minv[i] = 3.4e38f; mini[i] = 0; }

    const float* xs0 = &Xs[ty * 8];
    const float* es0 = &Es[tx * 8];

    for (int ch = 0; ch < 8; ++ch) {
        __syncthreads();  // previous chunk's Es reads done (and xsqs written, iter 0)
        // ---- load E chunk transposed into Es[d][code], coalesced global ----
        {
            const float* ebase = emb + (size_t)ch * 128 * D_;
            for (int q = tid; q < 128 * D_; q += 256) {
                int c = q >> 7;      // code within chunk
                int d = q & 127;     // dim
                Es[d * EPITCH + c] = ebase[q];
            }
            if (tid < 128) e2s[tid] = g_e2[ch * 128 + tid];
        }
        __syncthreads();

        unsigned long long acc[8][4];
        #pragma unroll
        for (int i = 0; i < 8; ++i)
            #pragma unroll
            for (int j = 0; j < 4; ++j) acc[i][j] = 0ULL;

        #pragma unroll 2
        for (int d = 0; d < 128; ++d) {
            float4 a0 = *reinterpret_cast<const float4*>(xs0 + d * 128);
            float4 a1 = *reinterpret_cast<const float4*>(xs0 + d * 128 + 4);
            unsigned long long b2[4];
            const unsigned long long* bp =
                reinterpret_cast<const unsigned long long*>(es0 + d * EPITCH);
            b2[0] = bp[0]; b2[1] = bp[1]; b2[2] = bp[2]; b2[3] = bp[3];
            unsigned long long ad[8];
            ad[0] = pack2(a0.x, a0.x); ad[1] = pack2(a0.y, a0.y);
            ad[2] = pack2(a0.z, a0.z); ad[3] = pack2(a0.w, a0.w);
            ad[4] = pack2(a1.x, a1.x); ad[5] = pack2(a1.y, a1.y);
            ad[6] = pack2(a1.z, a1.z); ad[7] = pack2(a1.w, a1.w);
            #pragma unroll
            for (int i = 0; i < 8; ++i)
                #pragma unroll
                for (int j = 0; j < 4; ++j)
                    acc[i][j] = ffma2(ad[i], b2[j], acc[i][j]);
        }

        // ---- fold chunk into running argmin with reference-matching rounding ----
        int cbase = ch * 128 + tx * 8;
        #pragma unroll
        for (int i = 0; i < 8; ++i) {
            float xsq = xsqs[ty * 8 + i];
            #pragma unroll
            for (int j = 0; j < 4; ++j) {
                float s0, s1;
                unpack2(acc[i][j], s0, s1);
                float A0 = xsq + e2s[tx * 8 + 2 * j];       // fl(|x|^2 + |e|^2)
                float A1 = xsq + e2s[tx * 8 + 2 * j + 1];
                float d0 = A0 - 2.0f * s0;                  // fl(A - 2*dot)
                float d1 = A1 - 2.0f * s1;
                if (d0 < minv[i]) { minv[i] = d0; mini[i] = cbase + 2 * j; }
                if (d1 < minv[i]) { minv[i] = d1; mini[i] = cbase + 2 * j + 1; }
            }
        }
    }

    // ---- cross-thread (tx) argmin reduction within 16-lane groups; ties -> smaller idx ----
    #pragma unroll
    for (int i = 0; i < 8; ++i) {
        #pragma unroll
        for (int off = 8; off >= 1; off >>= 1) {
            float v2 = __shfl_xor_sync(0xffffffffu, minv[i], off);
            int   i2 = __shfl_xor_sync(0xffffffffu, mini[i], off);
            if (v2 < minv[i] || (v2 == minv[i] && i2 < mini[i])) {
                minv[i] = v2; mini[i] = i2;
            }
        }
        if (tx == 0) {
            tokMin[ty * 8 + i] = minv[i];
            tokIdx[ty * 8 + i] = mini[i];
        }
    }
    __syncthreads();

    // ---- epilogue: idx out + histogram ----
    const int n0 = b * T_ + t0;
    if (tid < 128) {
        if (writeAux) idxOut[n0 + tid] = (float)tokIdx[tid];
        atomicAdd(&g_counts[tokIdx[tid]], 1.0f);
    }

    // ---- loss partial: sum of min distances (== sum |x - q|^2) ----
    {
        red[tid] = (tid < 128) ? tokMin[tid] : 0.0f;
        __syncthreads();
        #pragma unroll
        for (int s = 128; s > 0; s >>= 1) {
            if (tid < s) red[tid] += red[tid + s];
            __syncthreads();
        }
        if (tid == 0) atomicAdd(&g_losssum, red[0]);
    }

    // ---- dw scatter: g_dw[idx[t], :] += x[t, :] ----
    {
        int t    = tid >> 1;
        int half = tid & 1;
        int code = tokIdx[t];
        float* dst = &g_dw[(size_t)code * D_ + half * 64];
        const float* src = &Xs[(half * 64) * 128 + t];
        #pragma unroll 4
        for (int d = 0; d < 64; ++d)
            atomicAdd(&dst[d], src[d * 128]);
    }

    // ---- quantized output: out[b][d][t] = E[idx[t]][d] (coalesced writes, L2-hot gathers) ----
    {
        float* obase = out + ((size_t)b * D_) * T_ + t0;
        #pragma unroll 4
        for (int q = tid; q < 128 * D_; q += 256) {
            int d = q >> 7;
            int t = q & 127;
            obase[(size_t)d * T_ + t] = emb[(size_t)tokIdx[t] * D_ + d];
        }
    }
}

// -------- finalize A: n = sum(avg_cs), Laplace-smoothed cluster sizes, losses --------
__global__ void k_finalA(const float* __restrict__ hidC, float* __restrict__ lossOut, int writeAux) {
    __shared__ float red[K_];
    int k = threadIdx.x;
    const float onemd = 1.0f - DECAYF;
    float c   = g_counts[k];
    float h   = hidC[k];
    float hid = h - (h - c) * onemd;
    float avg = hid / onemd;               // denom = 1 - DECAY^1
    red[k] = avg;
    __syncthreads();
    for (int s = 512; s > 0; s >>= 1) {
        if (k < s) red[k] += red[k + s];
        __syncthreads();
    }
    float n  = red[0];
    float cs = (avg + EPSF) / (n + (float)K_ * EPSF) * n;
    g_cs[k] = cs;
    if (k == 0 && writeAux) {
        float M = g_losssum / (float)ND_;
        lossOut[0] = 0.25f * M;   // commit
        lossOut[1] = M;           // vq
    }
}

// -------- finalize B: new_embeddings = avg_dw / cs --------
__global__ void k_finalB(const float* __restrict__ hidDW, float* __restrict__ neOut) {
    int i = blockIdx.x * blockDim.x + threadIdx.x;
    if (i >= K_ * D_) return;
    const float onemd = 1.0f - DECAYF;
    float dwv = g_dw[i];
    float h   = hidDW[i];
    float hid = h - (h - dwv) * onemd;
    float avg = hid / onemd;
    neOut[i] = avg / g_cs[i >> 7];
}

extern "C" void kernel_launch(void* const* d_in, const int* in_sizes, int n_in,
                              void* d_out, int out_size) {
    const float* x     = (const float*)d_in[0];   // [64,128,2048]
    const float* emb   = (const float*)d_in[1];   // [1024,128]
    const float* hidDW = (const float*)d_in[2];   // [1024,128]
    const float* hidC  = (const float*)d_in[3];   // [1024]

    float* out = (float*)d_out;
    // Expected packing: out | loss_commit | loss_vq | idx | new_embeddings
    int writeAux = (out_size >= (ND_ + 2 + N_ + K_ * D_)) ? 1 : 0;
    float* lossOut = out + ND_;
    float* idxOut  = lossOut + 2;
    float* neOut   = idxOut + N_;

    const size_t smem = (size_t)(128 * 128 + 128 * EPITCH + 128 + 128 + 128 + 256 + 128) * 4;
    cudaFuncSetAttribute(k_main, cudaFuncAttributeMaxDynamicSharedMemorySize, (int)smem);

    k_zero<<<512, 256>>>();
    k_e2<<<32, 256>>>(emb);
    k_main<<<1024, 256, smem>>>(x, emb, out, idxOut, writeAux);
    k_finalA<<<1, 1024>>>(hidC, lossOut, writeAux);
    if (writeAux) k_finalB<<<512, 256>>>(hidDW, neOut);
}

// round 6
// speedup vs baseline: 1.4539x; 1.4539x over previous
#include <cuda_runtime.h>
#include <cstdint>

// Problem constants
#define B_   64
#define D_   128
#define T_   2048
#define K_   1024
#define N_   (B_ * T_)            // 131072 tokens
#define ND_  (N_ * D_)            // 16777216
#define DECAYF 0.99f
#define EPSF   1e-5f

// -------- device scratch (no allocations allowed) --------
__device__ float g_counts[K_];
__device__ float g_dw[K_ * D_];
__device__ float g_e2[K_];
__device__ float g_cs[K_];
__device__ float g_losssum;
__device__ float g_embT[D_ * K_];   // transposed codebook: [d][k]

// -------- packed f32x2 helpers (FFMA2 path: 2x fp32 FMA rate on sm_103a) --------
__device__ __forceinline__ unsigned long long pack2(float lo, float hi) {
    unsigned long long r;
    asm("mov.b64 %0, {%1, %2};" : "=l"(r) : "f"(lo), "f"(hi));
    return r;
}
__device__ __forceinline__ void unpack2(unsigned long long v, float& lo, float& hi) {
    asm("mov.b64 {%0, %1}, %2;" : "=f"(lo), "=f"(hi) : "l"(v));
}
__device__ __forceinline__ unsigned long long ffma2(unsigned long long a,
                                                    unsigned long long b,
                                                    unsigned long long c) {
    unsigned long long d;
    asm("fma.rn.f32x2 %0, %1, %2, %3;" : "=l"(d) : "l"(a), "l"(b), "l"(c));
    return d;
}

// -------- cp.async 16B --------
__device__ __forceinline__ void cp_async16(void* smem_dst, const void* gmem_src) {
    unsigned sdst = (unsigned)__cvta_generic_to_shared(smem_dst);
    asm volatile("cp.async.cg.shared.global [%0], [%1], 16;\n" :: "r"(sdst), "l"(gmem_src));
}
__device__ __forceinline__ void cp_async_commit() {
    asm volatile("cp.async.commit_group;\n" ::: "memory");
}
__device__ __forceinline__ void cp_async_wait0() {
    asm volatile("cp.async.wait_group 0;\n" ::: "memory");
}

// -------- zero scratch each launch (graph-replayable) --------
__global__ void k_zero() {
    int i = blockIdx.x * blockDim.x + threadIdx.x;
    if (i < K_ * D_) g_dw[i] = 0.0f;
    if (i < K_)      g_counts[i] = 0.0f;
    if (i == 0)      g_losssum = 0.0f;
}

// -------- |e_k|^2 per code (warp per code) --------
__global__ void k_e2(const float* __restrict__ emb) {
    int w    = (blockIdx.x * blockDim.x + threadIdx.x) >> 5;
    int lane = threadIdx.x & 31;
    for (int k = w; k < K_; k += (gridDim.x * blockDim.x) >> 5) {
        float s = 0.0f;
        const float* row = emb + (size_t)k * D_;
        for (int d = lane; d < D_; d += 32) {
            float v = row[d];
            s += v * v;
        }
        #pragma unroll
        for (int off = 16; off >= 1; off >>= 1)
            s += __shfl_xor_sync(0xffffffffu, s, off);
        if (lane == 0) g_e2[k] = s;
    }
}

// -------- one-time codebook transpose: g_embT[d][k] = emb[k][d] (tiled, conflict-free) --------
__global__ void k_prep(const float* __restrict__ emb) {
    __shared__ float tile[32][33];
    int k0 = blockIdx.x * 32;
    int d0 = blockIdx.y * 32;
    int lx = threadIdx.x;        // 0..31
    int ly = threadIdx.y;        // 0..7
    #pragma unroll
    for (int r = 0; r < 32; r += 8)
        tile[ly + r][lx] = emb[(size_t)(k0 + ly + r) * D_ + d0 + lx];
    __syncthreads();
    #pragma unroll
    for (int r = 0; r < 32; r += 8)
        g_embT[(size_t)(d0 + ly + r) * K_ + k0 + lx] = tile[lx][ly + r];
}

// -------- main fused kernel --------
// Block: 128 tokens vs all 1024 codes. 256 threads, 16x16 grid, 8 tok x 8 codes
// micro-tile with codes taken as stride-32 PAIRS (code = ch*128 + j*32 + tx*2)
// -> every LDS.64 of the E tile touches all 32 banks exactly once (conflict-free).
// E chunks are cp.async double-buffered from the pre-transposed g_embT.
// Distance comparison emulates the reference's fp32 rounding:
//   s_k = fl( fl(|x|^2 + |e_k|^2) - 2*dot_k ), strict-< / lowest-index tie-break.
__global__ __launch_bounds__(256, 1)
void k_main(const float* __restrict__ x, const float* __restrict__ emb,
            float* __restrict__ out, float* __restrict__ idxOut, int writeAux)
{
    extern __shared__ float sm[];
    float* Xs     = sm;                          // [128 d][128 tok]        16384
    float* Es     = Xs + 128 * 128;              // 2 x [128 d][128 codes]  32768
    float* e2all  = Es + 2 * 128 * 128;          // 1024
    float* tokMin = e2all + K_;                  // 128
    int*   tokIdx = (int*)(tokMin + 128);        // 128
    float* red    = (float*)(tokIdx + 128);      // 256
    float* xsqs   = red + 256;                   // 128

    const int tid  = threadIdx.x;
    const int tile = blockIdx.x;
    const int b    = tile >> 4;
    const int t0   = (tile & 15) << 7;

    const float* xbase = x + ((size_t)b * D_) * T_ + t0;

    // ---- kick off E chunk 0 prefetch immediately ----
    {
        #pragma unroll
        for (int u = 0; u < 16; ++u) {
            int q = tid + u * 256;           // 4096 16B units (64KB)
            int d = q >> 5;
            int o = (q & 31) * 4;
            cp_async16(Es + d * 128 + o, g_embT + (size_t)d * K_ + o);
        }
        cp_async_commit();
    }

    // ---- load X tile [d][tok] (coalesced float4) + e2 table ----
    #pragma unroll
    for (int r = 0; r < 16; ++r) {
        int f4 = tid + 256 * r;
        int d  = f4 >> 5;
        int tt = (f4 & 31) * 4;
        float4 v = *reinterpret_cast<const float4*>(xbase + (size_t)d * T_ + tt);
        *reinterpret_cast<float4*>(&Xs[d * 128 + tt]) = v;
    }
    #pragma unroll
    for (int i = tid; i < K_; i += 256) e2all[i] = g_e2[i];
    __syncthreads();

    // ---- per-token |x|^2: two sequential 64-term halves, then combine ----
    {
        int t    = tid >> 1;
        int half = tid & 1;
        float s = 0.0f;
        const float* col = &Xs[(half * 64) * 128 + t];
        #pragma unroll 8
        for (int d = 0; d < 64; ++d) {
            float v = col[d * 128];
            s += v * v;
        }
        red[tid] = s;
    }
    __syncthreads();
    if (tid < 128) xsqs[tid] = red[2 * tid] + red[2 * tid + 1];

    const int tx = tid & 15;
    const int ty = tid >> 4;

    float minv[8];
    int   mini[8];
    #pragma unroll
    for (int i = 0; i < 8; ++i) { minv[i] = 3.4e38f; mini[i] = 0; }

    const float* xrow = &Xs[ty * 8];

    for (int ch = 0; ch < 8; ++ch) {
        cp_async_wait0();
        __syncthreads();   // chunk data visible; previous compute done; xsqs ready (iter 0)

        // prefetch next chunk into the other buffer (overlaps with compute below)
        if (ch + 1 < 8) {
            float* nb = Es + ((ch + 1) & 1) * (128 * 128);
            const float* src = g_embT + (ch + 1) * 128;
            #pragma unroll
            for (int u = 0; u < 16; ++u) {
                int q = tid + u * 256;
                int d = q >> 5;
                int o = (q & 31) * 4;
                cp_async16(nb + d * 128 + o, src + (size_t)d * K_ + o);
            }
            cp_async_commit();
        }

        const float* erow = Es + (ch & 1) * (128 * 128) + tx * 2;

        unsigned long long acc[8][4];
        #pragma unroll
        for (int i = 0; i < 8; ++i)
            #pragma unroll
            for (int j = 0; j < 4; ++j) acc[i][j] = 0ULL;

        #pragma unroll 2
        for (int d = 0; d < 128; ++d) {
            float4 a0 = *reinterpret_cast<const float4*>(xrow + d * 128);
            float4 a1 = *reinterpret_cast<const float4*>(xrow + d * 128 + 4);
            const unsigned long long* bp =
                reinterpret_cast<const unsigned long long*>(erow + d * 128);
            unsigned long long bv[4];
            bv[0] = bp[0]; bv[1] = bp[16]; bv[2] = bp[32]; bv[3] = bp[48];
            unsigned long long ad[8];
            ad[0] = pack2(a0.x, a0.x); ad[1] = pack2(a0.y, a0.y);
            ad[2] = pack2(a0.z, a0.z); ad[3] = pack2(a0.w, a0.w);
            ad[4] = pack2(a1.x, a1.x); ad[5] = pack2(a1.y, a1.y);
            ad[6] = pack2(a1.z, a1.z); ad[7] = pack2(a1.w, a1.w);
            #pragma unroll
            for (int i = 0; i < 8; ++i)
                #pragma unroll
                for (int j = 0; j < 4; ++j)
                    acc[i][j] = ffma2(ad[i], bv[j], acc[i][j]);
        }

        // ---- fold chunk into running argmin with reference-matching rounding ----
        // Thread's codes: ch*128 + j*32 + tx*2 (+1) — ascending in (ch, j), so
        // strict-< keeps the lowest index on rounded ties.
        #pragma unroll
        for (int i = 0; i < 8; ++i) {
            float xsq = xsqs[ty * 8 + i];
            #pragma unroll
            for (int j = 0; j < 4; ++j) {
                float s0, s1;
                unpack2(acc[i][j], s0, s1);
                int   c0 = ch * 128 + j * 32 + tx * 2;
                float A0 = xsq + e2all[c0];
                float A1 = xsq + e2all[c0 + 1];
                float d0 = A0 - 2.0f * s0;
                float d1 = A1 - 2.0f * s1;
                if (d0 < minv[i]) { minv[i] = d0; mini[i] = c0; }
                if (d1 < minv[i]) { minv[i] = d1; mini[i] = c0 + 1; }
            }
        }
    }

    // ---- cross-thread (tx) argmin reduction within 16-lane groups; ties -> smaller idx ----
    #pragma unroll
    for (int i = 0; i < 8; ++i) {
        #pragma unroll
        for (int off = 8; off >= 1; off >>= 1) {
            float v2 = __shfl_xor_sync(0xffffffffu, minv[i], off);
            int   i2 = __shfl_xor_sync(0xffffffffu, mini[i], off);
            if (v2 < minv[i] || (v2 == minv[i] && i2 < mini[i])) {
                minv[i] = v2; mini[i] = i2;
            }
        }
        if (tx == 0) {
            tokMin[ty * 8 + i] = minv[i];
            tokIdx[ty * 8 + i] = mini[i];
        }
    }
    __syncthreads();

    // ---- epilogue: idx out + histogram ----
    const int n0 = b * T_ + t0;
    if (tid < 128) {
        if (writeAux) idxOut[n0 + tid] = (float)tokIdx[tid];
        atomicAdd(&g_counts[tokIdx[tid]], 1.0f);
    }

    // ---- loss partial: sum of min distances (== sum |x - q|^2) ----
    {
        red[tid] = (tid < 128) ? tokMin[tid] : 0.0f;
        __syncthreads();
        #pragma unroll
        for (int s = 128; s > 0; s >>= 1) {
            if (tid < s) red[tid] += red[tid + s];
            __syncthreads();
        }
        if (tid == 0) atomicAdd(&g_losssum, red[0]);
    }

    // ---- dw scatter: g_dw[idx[t], :] += x[t, :]  (vectorized red.v4, no return) ----
    {
        int t    = tid >> 1;
        int half = tid & 1;
        int code = tokIdx[t];
        float* dst = &g_dw[(size_t)code * D_ + half * 64];
        const float* src = &Xs[(half * 64) * 128 + t];
        #pragma unroll
        for (int d = 0; d < 64; d += 4) {
            float v0 = src[(d + 0) * 128];
            float v1 = src[(d + 1) * 128];
            float v2 = src[(d + 2) * 128];
            float v3 = src[(d + 3) * 128];
            asm volatile("red.global.add.v4.f32 [%0], {%1, %2, %3, %4};"
                         :: "l"(dst + d), "f"(v0), "f"(v1), "f"(v2), "f"(v3)
                         : "memory");
        }
    }

    // ---- quantized output: out[b][d][t] = E[idx[t]][d] (coalesced writes, L2-hot gathers) ----
    {
        float* obase = out + ((size_t)b * D_) * T_ + t0;
        #pragma unroll 4
        for (int q = tid; q < 128 * D_; q += 256) {
            int d = q >> 7;
            int t = q & 127;
            obase[(size_t)d * T_ + t] = emb[(size_t)tokIdx[t] * D_ + d];
        }
    }
}

// -------- finalize A: n = sum(avg_cs), Laplace-smoothed cluster sizes, losses --------
__global__ void k_finalA(const float* __restrict__ hidC, float* __restrict__ lossOut, int writeAux) {
    __shared__ float red[K_];
    int k = threadIdx.x;
    const float onemd = 1.0f - DECAYF;
    float c   = g_counts[k];
    float h   = hidC[k];
    float hid = h - (h - c) * onemd;
    float avg = hid / onemd;               // denom = 1 - DECAY^1
    red[k] = avg;
    __syncthreads();
    for (int s = 512; s > 0; s >>= 1) {
        if (k < s) red[k] += red[k + s];
        __syncthreads();
    }
    float n  = red[0];
    float cs = (avg + EPSF) / (n + (float)K_ * EPSF) * n;
    g_cs[k] = cs;
    if (k == 0 && writeAux) {
        float M = g_losssum / (float)ND_;
        lossOut[0] = 0.25f * M;   // commit
        lossOut[1] = M;           // vq
    }
}

// -------- finalize B: new_embeddings = avg_dw / cs --------
__global__ void k_finalB(const float* __restrict__ hidDW, float* __restrict__ neOut) {
    int i = blockIdx.x * blockDim.x + threadIdx.x;
    if (i >= K_ * D_) return;
    const float onemd = 1.0f - DECAYF;
    float dwv = g_dw[i];
    float h   = hidDW[i];
    float hid = h - (h - dwv) * onemd;
    float avg = hid / onemd;
    neOut[i] = avg / g_cs[i >> 7];
}

extern "C" void kernel_launch(void* const* d_in, const int* in_sizes, int n_in,
                              void* d_out, int out_size) {
    const float* x     = (const float*)d_in[0];   // [64,128,2048]
    const float* emb   = (const float*)d_in[1];   // [1024,128]
    const float* hidDW = (const float*)d_in[2];   // [1024,128]
    const float* hidC  = (const float*)d_in[3];   // [1024]

    float* out = (float*)d_out;
    // Expected packing: out | loss_commit | loss_vq | idx | new_embeddings
    int writeAux = (out_size >= (ND_ + 2 + N_ + K_ * D_)) ? 1 : 0;
    float* lossOut = out + ND_;
    float* idxOut  = lossOut + 2;
    float* neOut   = idxOut + N_;

    const size_t smem =
        (size_t)(128 * 128 + 2 * 128 * 128 + K_ + 128 + 128 + 256 + 128) * 4;
    cudaFuncSetAttribute(k_main, cudaFuncAttributeMaxDynamicSharedMemorySize, (int)smem);

    k_zero<<<512, 256>>>();
    k_e2<<<32, 256>>>(emb);
    {
        dim3 g(K_ / 32, D_ / 32), blk(32, 8);
        k_prep<<<g, blk>>>(emb);
    }
    k_main<<<1024, 256, smem>>>(x, emb, out, idxOut, writeAux);
    k_finalA<<<1, 1024>>>(hidC, lossOut, writeAux);
    if (writeAux) k_finalB<<<512, 256>>>(hidDW, neOut);
}